// round 6
// baseline (speedup 1.0000x reference)
#include <cuda_runtime.h>
#include <math.h>

#define NB 2
#define NC 128
#define HG 32
#define L 1024
#define NCOLS 2048   // NC * 16

// ---- scratch (device globals; no allocation allowed) ----
__device__ float g_fd[NB*NC*L];
__device__ float g_bd[NB*NC*L];
__device__ float g_ssq[NB*L];
__device__ float g_rnorm[NB*L];
__device__ float g_corr[NB*L*L];   // M[q,p] = sum_c bd[c,q]*fd[c,p]
__device__ float g_sc[NB*L*L];     // normalized 9-tap scores
__device__ float g_t1[NB*L*L];     // fuse pass 1
__device__ float g_fu[NB*L*L];     // fuse pass 2
__device__ float g_mmk[L];
__device__ float g_attn[NB*L*L];   // [b][q][p]
__device__ float g_W[NB*L*NCOLS];  // raw_w patches [b][q][c*16+u*4+v]
__device__ float g_OP[NB*L*NCOLS]; // deconv GEMM output [b][p][n]

// ---- 1. downsample by 2 ----
__global__ void k_down(const float* __restrict__ f, const float* __restrict__ b) {
    int idx = blockIdx.x * blockDim.x + threadIdx.x;
    if (idx >= NB*NC*L) return;
    int x = idx & 31, y = (idx >> 5) & 31, c = (idx >> 10) & 127, bb = idx >> 17;
    size_t base = ((size_t)(bb * NC + c)) * 4096 + (size_t)(2*y) * 64 + 2*x;
    g_fd[idx] = f[base];
    g_bd[idx] = b[base];
}

// ---- 2. per-pixel sum over c of bd^2 ----
__global__ void k_ssq() {
    int idx = blockIdx.x * blockDim.x + threadIdx.x;
    if (idx >= NB*L) return;
    int bb = idx >> 10, q = idx & 1023;
    float s = 0.f;
    const float* p = g_bd + (size_t)bb * NC * L + q;
    #pragma unroll 8
    for (int c = 0; c < NC; c++) { float v = p[(size_t)c * L]; s += v * v; }
    g_ssq[idx] = s;
}

// ---- 3. patch inverse norms (3x3, zero pad) ----
__global__ void k_rnorm() {
    int idx = blockIdx.x * blockDim.x + threadIdx.x;
    if (idx >= NB*L) return;
    int bb = idx >> 10, q = idx & 1023;
    int qy = q >> 5, qx = q & 31;
    float s = 1152.0f * 0.0001f;
    for (int dy = -1; dy <= 1; dy++)
      for (int dx = -1; dx <= 1; dx++) {
        int y = qy + dy, x = qx + dx;
        if (y >= 0 && y < HG && x >= 0 && x < HG) s += g_ssq[bb*L + y*HG + x];
      }
    g_rnorm[idx] = 1.0f / sqrtf(s);
}

// ---- generic TN fp32 SGEMM: C[M,N] = sum_k A[k,M] * B[k,N] ----
__global__ void __launch_bounds__(256)
sgemm_tn(const float* __restrict__ A, const float* __restrict__ B, float* __restrict__ C,
         int M, int N, int K, size_t sA, size_t sB, size_t sC) {
    const int BM = 128, BN = 128, BK = 8;
    __shared__ float As[BK][BM];
    __shared__ float Bs[BK][BN];
    A += (size_t)blockIdx.z * sA;
    B += (size_t)blockIdx.z * sB;
    C += (size_t)blockIdx.z * sC;
    int bm = blockIdx.y * BM, bn = blockIdx.x * BN;
    int tid = threadIdx.x;
    int tx = tid & 15, ty = tid >> 4;
    int arow = tid >> 5, acol = (tid & 31) << 2;
    float acc[8][8];
    #pragma unroll
    for (int i = 0; i < 8; i++)
      #pragma unroll
      for (int j = 0; j < 8; j++) acc[i][j] = 0.f;

    for (int k0 = 0; k0 < K; k0 += BK) {
        float4 av = *(const float4*)(A + (size_t)(k0 + arow) * M + bm + acol);
        float4 bv = *(const float4*)(B + (size_t)(k0 + arow) * N + bn + acol);
        *(float4*)(&As[arow][acol]) = av;
        *(float4*)(&Bs[arow][acol]) = bv;
        __syncthreads();
        #pragma unroll
        for (int k = 0; k < BK; k++) {
            float ar[8], br[8];
            *(float4*)(ar)     = *(float4*)(&As[k][ty * 8]);
            *(float4*)(ar + 4) = *(float4*)(&As[k][ty * 8 + 4]);
            *(float4*)(br)     = *(float4*)(&Bs[k][tx * 8]);
            *(float4*)(br + 4) = *(float4*)(&Bs[k][tx * 8 + 4]);
            #pragma unroll
            for (int i = 0; i < 8; i++)
              #pragma unroll
              for (int j = 0; j < 8; j++) acc[i][j] += ar[i] * br[j];
        }
        __syncthreads();
    }
    #pragma unroll
    for (int i = 0; i < 8; i++) {
        float* cp = C + (size_t)(bm + ty * 8 + i) * N + bn + tx * 8;
        *(float4*)(cp)     = make_float4(acc[i][0], acc[i][1], acc[i][2], acc[i][3]);
        *(float4*)(cp + 4) = make_float4(acc[i][4], acc[i][5], acc[i][6], acc[i][7]);
    }
}

// ---- 5. 9-tap diagonal patch stencil + normalize ----
__global__ void k_scores() {
    int idx = blockIdx.x * blockDim.x + threadIdx.x;
    if (idx >= NB*L*L) return;
    int px = idx & 31, py = (idx >> 5) & 31, qx = (idx >> 10) & 31, qy = (idx >> 15) & 31;
    int bb = idx >> 20;
    const float* M = g_corr + (size_t)bb * L * L;
    float s = 0.f;
    #pragma unroll
    for (int dy = -1; dy <= 1; dy++) {
        int qy2 = qy + dy, py2 = py + dy;
        if (qy2 < 0 || qy2 >= HG || py2 < 0 || py2 >= HG) continue;
        #pragma unroll
        for (int dx = -1; dx <= 1; dx++) {
            int qx2 = qx + dx, px2 = px + dx;
            if (qx2 < 0 || qx2 >= HG || px2 < 0 || px2 >= HG) continue;
            s += M[(size_t)(qy2 * HG + qx2) * L + (py2 * HG + px2)];
        }
    }
    g_sc[idx] = s * g_rnorm[bb * L + qy * HG + qx];
}

// ---- 6. fuse pass 1: diagonal 3-tap on flattened (1024,1024) ----
__global__ void k_fuse1() {
    int idx = blockIdx.x * blockDim.x + threadIdx.x;
    if (idx >= NB*L*L) return;
    int j = idx & 1023, i = (idx >> 10) & 1023;
    float s = g_sc[idx];
    if (i > 0 && j > 0)       s += g_sc[idx - L - 1];
    if (i < 1023 && j < 1023) s += g_sc[idx + L + 1];
    g_t1[idx] = s;
}

// ---- 7. fuse pass 2: transposed flattening, diagonal 3-tap, untranspose ----
__global__ void k_fuse2() {
    int idx = blockIdx.x * blockDim.x + threadIdx.x;
    if (idx >= NB*L*L) return;
    int wf = idx & 31, hf = (idx >> 5) & 31, wb = (idx >> 10) & 31, hb = (idx >> 15) & 31;
    int bb = idx >> 20;
    int i2b = wb * HG + hb, j2b = wf * HG + hf;
    const float* T = g_t1 + (size_t)bb * L * L;
    float s = 0.f;
    #pragma unroll
    for (int d = -1; d <= 1; d++) {
        int i2 = i2b + d, j2 = j2b + d;
        if (i2 < 0 || i2 >= L || j2 < 0 || j2 >= L) continue;
        int hb2 = i2 & 31, wb2 = i2 >> 5, hf2 = j2 & 31, wf2 = j2 >> 5;
        s += T[(size_t)(hb2 * HG + wb2) * L + (hf2 * HG + wf2)];
    }
    g_fu[idx] = s;
}

// ---- 8. mask gate (batch 0 of mask) ----
__global__ void k_mm(const float* __restrict__ mask) {
    int q = blockIdx.x * blockDim.x + threadIdx.x;
    if (q >= L) return;
    int qy = q >> 5, qx = q & 31;
    float s = 0.f;
    for (int dy = -1; dy <= 1; dy++)
      for (int dx = -1; dx <= 1; dx++) {
        int y = qy + dy, x = qx + dx;
        if (y >= 0 && y < HG && x >= 0 && x < HG)
            s += mask[(size_t)(8 * y) * 256 + 8 * x];
      }
    g_mmk[q] = (s == 0.0f) ? 1.0f : 0.0f;
}

// ---- 9. softmax over q (axis of length 1024) per (b,p) ----
__global__ void k_softmax() {
    int bb = blockIdx.y;
    int p = blockIdx.x * 32 + threadIdx.x;
    int tx = threadIdx.x, ty = threadIdx.y;
    __shared__ float red[8][32];
    const float* src = g_fu + (size_t)bb * L * L;
    float* dst = g_attn + (size_t)bb * L * L;
    float mx = -1e30f;
    for (int q = ty; q < L; q += 8) {
        float v = src[(size_t)q * L + p] * g_mmk[q] * 10.0f;
        mx = fmaxf(mx, v);
    }
    red[ty][tx] = mx; __syncthreads();
    if (ty == 0) {
        float m = red[0][tx];
        #pragma unroll
        for (int k = 1; k < 8; k++) m = fmaxf(m, red[k][tx]);
        red[0][tx] = m;
    }
    __syncthreads();
    mx = red[0][tx];
    __syncthreads();
    float sm = 0.f;
    for (int q = ty; q < L; q += 8) {
        float v = src[(size_t)q * L + p] * g_mmk[q] * 10.0f;
        float e = expf(v - mx);
        dst[(size_t)q * L + p] = e;
        sm += e;
    }
    red[ty][tx] = sm; __syncthreads();
    if (ty == 0) {
        float s = 0.f;
        #pragma unroll
        for (int k = 0; k < 8; k++) s += red[k][tx];
        red[0][tx] = s;
    }
    __syncthreads();
    float inv = 1.0f / red[0][tx];
    for (int q = ty; q < L; q += 8)
        dst[(size_t)q * L + p] *= inv * g_mmk[q];
}

// ---- 10. build raw_w patch matrix W[b][q][c*16+u*4+v] ----
__global__ void k_buildW(const float* __restrict__ b_in) {
    int idx = blockIdx.x * blockDim.x + threadIdx.x;
    if (idx >= NB*L*NCOLS) return;
    int n = idx & (NCOLS - 1);
    int v = n & 3, u = (n >> 2) & 3, c = n >> 4;
    int q = (idx >> 11) & 1023;
    int bb = idx >> 21;
    int qy = q >> 5, qx = q & 31;
    int by = 2 * qy + u - 1, bx = 2 * qx + v - 1;
    float val = 0.f;
    if (by >= 0 && by < 64 && bx >= 0 && bx < 64)
        val = b_in[((size_t)(bb * NC + c)) * 4096 + (size_t)by * 64 + bx];
    g_W[idx] = val;
}

// ---- 12. overlap-add gather (deconv epilogue) ----
__global__ void k_gather(float* __restrict__ out) {
    int idx = blockIdx.x * blockDim.x + threadIdx.x;
    if (idx >= NB*NC*4096) return;
    int ox = idx & 63, oy = (idx >> 6) & 63, c = (idx >> 12) & 127, bb = idx >> 19;
    float s = 0.f;
    int ay = (oy + 1) & 1, ax = (ox + 1) & 1;
    #pragma unroll
    for (int uu = 0; uu < 2; uu++) {
        int u = ay + 2 * uu;
        int t = oy + 1 - u;
        if (t < 0) continue;
        int py = t >> 1;
        if (py >= HG) continue;
        #pragma unroll
        for (int vv = 0; vv < 2; vv++) {
            int v = ax + 2 * vv;
            int t2 = ox + 1 - v;
            if (t2 < 0) continue;
            int px = t2 >> 1;
            if (px >= HG) continue;
            s += g_OP[((size_t)bb * L + py * HG + px) * NCOLS + c * 16 + u * 4 + v];
        }
    }
    out[idx] = 0.25f * s;
}

extern "C" void kernel_launch(void* const* d_in, const int* in_sizes, int n_in,
                              void* d_out, int out_size) {
    (void)in_sizes; (void)n_in; (void)out_size;
    const float* f    = (const float*)d_in[0];
    const float* b    = (const float*)d_in[1];
    const float* mask = (const float*)d_in[2];
    float* out = (float*)d_out;

    float *p_fd, *p_bd, *p_corr, *p_attn, *p_W, *p_OP;
    cudaGetSymbolAddress((void**)&p_fd,   g_fd);
    cudaGetSymbolAddress((void**)&p_bd,   g_bd);
    cudaGetSymbolAddress((void**)&p_corr, g_corr);
    cudaGetSymbolAddress((void**)&p_attn, g_attn);
    cudaGetSymbolAddress((void**)&p_W,    g_W);
    cudaGetSymbolAddress((void**)&p_OP,   g_OP);

    k_down<<<(NB*NC*L + 255) / 256, 256>>>(f, b);
    k_ssq<<<(NB*L + 255) / 256, 256>>>();
    k_rnorm<<<(NB*L + 255) / 256, 256>>>();

    // GEMM1: corr[q,p] = sum_c bd[c,q] * fd[c,p]   (M=N=1024, K=128)
    {
        dim3 grid(L / 128, L / 128, NB);
        sgemm_tn<<<grid, 256>>>(p_bd, p_fd, p_corr, L, L, NC,
                                (size_t)NC * L, (size_t)NC * L, (size_t)L * L);
    }

    k_scores<<<(NB*L*L + 255) / 256, 256>>>();
    k_fuse1<<<(NB*L*L + 255) / 256, 256>>>();
    k_fuse2<<<(NB*L*L + 255) / 256, 256>>>();
    k_mm<<<(L + 255) / 256, 256>>>(mask);
    {
        dim3 grid(L / 32, NB);
        dim3 blk(32, 8);
        k_softmax<<<grid, blk>>>();
    }
    k_buildW<<<(NB*L*NCOLS + 255) / 256, 256>>>(b);

    // GEMM2: OP[p,n] = sum_q attn[q,p] * W[q,n]   (M=1024, N=2048, K=1024)
    {
        dim3 grid(NCOLS / 128, L / 128, NB);
        sgemm_tn<<<grid, 256>>>(p_attn, p_W, p_OP, L, NCOLS, L,
                                (size_t)L * L, (size_t)L * NCOLS, (size_t)L * NCOLS);
    }

    k_gather<<<(NB*NC*4096 + 255) / 256, 256>>>(out);
}

// round 7
// speedup vs baseline: 2.0679x; 2.0679x over previous
#include <cuda_runtime.h>
#include <math.h>
#include <stdint.h>

#define NB 2
#define NC 128
#define HG 32
#define L 1024
#define NCOLS 2048   // NC * 16

// ---- scratch (device globals; no allocation allowed) ----
__device__ float g_fd[NB*NC*L];
__device__ float g_bd[NB*NC*L];
__device__ float g_ssq[NB*L];
__device__ float g_rnorm[NB*L];
__device__ float g_corr[NB*L*L];   // M[q,p] = sum_c bd[c,q]*fd[c,p]
__device__ float g_sc[NB*L*L];     // normalized 9-tap scores
__device__ float g_t1[NB*L*L];     // fuse pass 1 / later: transposed fuse output [p][q]
__device__ float g_fu[NB*L*L];     // fuse pass 2 output [q][p]
__device__ float g_mmk[L];
__device__ float g_attn[NB*L*L];   // attn TRANSPOSED: [b][p][q], tf32-rounded
__device__ float g_W[NB*L*NCOLS];  // raw_w patches [b][q][c*16+u*4+v], tf32-rounded
__device__ float g_OP[NB*L*NCOLS]; // deconv GEMM output [b][p][n]

// ---- helpers ----
__device__ __forceinline__ float to_tf32(float x) {
    uint32_t u;
    asm("cvt.rna.tf32.f32 %0, %1;" : "=r"(u) : "f"(x));
    return __uint_as_float(u);
}
__device__ __forceinline__ void cp_async16(uint32_t s, const void* g) {
    asm volatile("cp.async.cg.shared.global [%0], [%1], 16;" :: "r"(s), "l"(g));
}
__device__ __forceinline__ void mma_tf32(float* c, const uint32_t* a, const uint32_t* b) {
    asm volatile(
        "mma.sync.aligned.m16n8k8.row.col.f32.tf32.tf32.f32 "
        "{%0,%1,%2,%3}, {%4,%5,%6,%7}, {%8,%9}, {%0,%1,%2,%3};"
        : "+f"(c[0]), "+f"(c[1]), "+f"(c[2]), "+f"(c[3])
        : "r"(a[0]), "r"(a[1]), "r"(a[2]), "r"(a[3]), "r"(b[0]), "r"(b[1]));
}

// ---- 1. downsample by 2 ----
__global__ void k_down(const float* __restrict__ f, const float* __restrict__ b) {
    int idx = blockIdx.x * blockDim.x + threadIdx.x;
    if (idx >= NB*NC*L) return;
    int x = idx & 31, y = (idx >> 5) & 31, c = (idx >> 10) & 127, bb = idx >> 17;
    size_t base = ((size_t)(bb * NC + c)) * 4096 + (size_t)(2*y) * 64 + 2*x;
    g_fd[idx] = f[base];
    g_bd[idx] = b[base];
}

// ---- 2. per-pixel sum over c of bd^2 ----
__global__ void k_ssq() {
    int idx = blockIdx.x * blockDim.x + threadIdx.x;
    if (idx >= NB*L) return;
    int bb = idx >> 10, q = idx & 1023;
    float s = 0.f;
    const float* p = g_bd + (size_t)bb * NC * L + q;
    #pragma unroll 8
    for (int c = 0; c < NC; c++) { float v = p[(size_t)c * L]; s += v * v; }
    g_ssq[idx] = s;
}

// ---- 3. patch inverse norms (3x3, zero pad) ----
__global__ void k_rnorm() {
    int idx = blockIdx.x * blockDim.x + threadIdx.x;
    if (idx >= NB*L) return;
    int bb = idx >> 10, q = idx & 1023;
    int qy = q >> 5, qx = q & 31;
    float s = 1152.0f * 0.0001f;
    for (int dy = -1; dy <= 1; dy++)
      for (int dx = -1; dx <= 1; dx++) {
        int y = qy + dy, x = qx + dx;
        if (y >= 0 && y < HG && x >= 0 && x < HG) s += g_ssq[bb*L + y*HG + x];
      }
    g_rnorm[idx] = 1.0f / sqrtf(s);
}

// ---- generic TN fp32 SGEMM (kept for GEMM1; exp(30x) downstream needs fp32) ----
__global__ void __launch_bounds__(256)
sgemm_tn(const float* __restrict__ A, const float* __restrict__ B, float* __restrict__ C,
         int M, int N, int K, size_t sA, size_t sB, size_t sC) {
    const int BM = 128, BN = 128, BK = 8;
    __shared__ float As[BK][BM];
    __shared__ float Bs[BK][BN];
    A += (size_t)blockIdx.z * sA;
    B += (size_t)blockIdx.z * sB;
    C += (size_t)blockIdx.z * sC;
    int bm = blockIdx.y * BM, bn = blockIdx.x * BN;
    int tid = threadIdx.x;
    int tx = tid & 15, ty = tid >> 4;
    int arow = tid >> 5, acol = (tid & 31) << 2;
    float acc[8][8];
    #pragma unroll
    for (int i = 0; i < 8; i++)
      #pragma unroll
      for (int j = 0; j < 8; j++) acc[i][j] = 0.f;

    for (int k0 = 0; k0 < K; k0 += BK) {
        float4 av = *(const float4*)(A + (size_t)(k0 + arow) * M + bm + acol);
        float4 bv = *(const float4*)(B + (size_t)(k0 + arow) * N + bn + acol);
        *(float4*)(&As[arow][acol]) = av;
        *(float4*)(&Bs[arow][acol]) = bv;
        __syncthreads();
        #pragma unroll
        for (int k = 0; k < BK; k++) {
            float ar[8], br[8];
            *(float4*)(ar)     = *(float4*)(&As[k][ty * 8]);
            *(float4*)(ar + 4) = *(float4*)(&As[k][ty * 8 + 4]);
            *(float4*)(br)     = *(float4*)(&Bs[k][tx * 8]);
            *(float4*)(br + 4) = *(float4*)(&Bs[k][tx * 8 + 4]);
            #pragma unroll
            for (int i = 0; i < 8; i++)
              #pragma unroll
              for (int j = 0; j < 8; j++) acc[i][j] += ar[i] * br[j];
        }
        __syncthreads();
    }
    #pragma unroll
    for (int i = 0; i < 8; i++) {
        float* cp = C + (size_t)(bm + ty * 8 + i) * N + bn + tx * 8;
        *(float4*)(cp)     = make_float4(acc[i][0], acc[i][1], acc[i][2], acc[i][3]);
        *(float4*)(cp + 4) = make_float4(acc[i][4], acc[i][5], acc[i][6], acc[i][7]);
    }
}

// ---- 5. 9-tap diagonal patch stencil + normalize ----
__global__ void k_scores() {
    int idx = blockIdx.x * blockDim.x + threadIdx.x;
    if (idx >= NB*L*L) return;
    int px = idx & 31, py = (idx >> 5) & 31, qx = (idx >> 10) & 31, qy = (idx >> 15) & 31;
    int bb = idx >> 20;
    const float* M = g_corr + (size_t)bb * L * L;
    float s = 0.f;
    #pragma unroll
    for (int dy = -1; dy <= 1; dy++) {
        int qy2 = qy + dy, py2 = py + dy;
        if (qy2 < 0 || qy2 >= HG || py2 < 0 || py2 >= HG) continue;
        #pragma unroll
        for (int dx = -1; dx <= 1; dx++) {
            int qx2 = qx + dx, px2 = px + dx;
            if (qx2 < 0 || qx2 >= HG || px2 < 0 || px2 >= HG) continue;
            s += M[(size_t)(qy2 * HG + qx2) * L + (py2 * HG + px2)];
        }
    }
    g_sc[idx] = s * g_rnorm[bb * L + qy * HG + qx];
}

// ---- 6. fuse pass 1: diagonal 3-tap on flattened (1024,1024) ----
__global__ void k_fuse1() {
    int idx = blockIdx.x * blockDim.x + threadIdx.x;
    if (idx >= NB*L*L) return;
    int j = idx & 1023, i = (idx >> 10) & 1023;
    float s = g_sc[idx];
    if (i > 0 && j > 0)       s += g_sc[idx - L - 1];
    if (i < 1023 && j < 1023) s += g_sc[idx + L + 1];
    g_t1[idx] = s;
}

// ---- 7. fuse pass 2: transposed flattening, diagonal 3-tap, untranspose ----
__global__ void k_fuse2() {
    int idx = blockIdx.x * blockDim.x + threadIdx.x;
    if (idx >= NB*L*L) return;
    int wf = idx & 31, hf = (idx >> 5) & 31, wb = (idx >> 10) & 31, hb = (idx >> 15) & 31;
    int bb = idx >> 20;
    int i2b = wb * HG + hb, j2b = wf * HG + hf;
    const float* T = g_t1 + (size_t)bb * L * L;
    float s = 0.f;
    #pragma unroll
    for (int d = -1; d <= 1; d++) {
        int i2 = i2b + d, j2 = j2b + d;
        if (i2 < 0 || i2 >= L || j2 < 0 || j2 >= L) continue;
        int hb2 = i2 & 31, wb2 = i2 >> 5, hf2 = j2 & 31, wf2 = j2 >> 5;
        s += T[(size_t)(hb2 * HG + wb2) * L + (hf2 * HG + wf2)];
    }
    g_fu[idx] = s;
}

// ---- 7b. transpose g_fu [q][p] -> g_t1 [p][q] (g_t1 free after fuse2) ----
__global__ void k_transpose() {
    __shared__ float t[32][33];
    int bb = blockIdx.z;
    int xs = blockIdx.x * 32, ys = blockIdx.y * 32;
    const float* src = g_fu + (size_t)bb * L * L;
    float* dst = g_t1 + (size_t)bb * L * L;
    int tx = threadIdx.x, ty = threadIdx.y;   // 32 x 8
    #pragma unroll
    for (int j = 0; j < 4; j++)
        t[ty + 8*j][tx] = src[(size_t)(ys + ty + 8*j) * L + xs + tx];
    __syncthreads();
    #pragma unroll
    for (int j = 0; j < 4; j++)
        dst[(size_t)(xs + ty + 8*j) * L + ys + tx] = t[tx][ty + 8*j];
}

// ---- 8. mask gate (batch 0 of mask) ----
__global__ void k_mm(const float* __restrict__ mask) {
    int q = blockIdx.x * blockDim.x + threadIdx.x;
    if (q >= L) return;
    int qy = q >> 5, qx = q & 31;
    float s = 0.f;
    for (int dy = -1; dy <= 1; dy++)
      for (int dx = -1; dx <= 1; dx++) {
        int y = qy + dy, x = qx + dx;
        if (y >= 0 && y < HG && x >= 0 && x < HG)
            s += mask[(size_t)(8 * y) * 256 + 8 * x];
      }
    g_mmk[q] = (s == 0.0f) ? 1.0f : 0.0f;
}

// ---- 9. row softmax over q: reads g_t1 [p][q], writes g_attn [p][q] (tf32) ----
__global__ void __launch_bounds__(256) k_softmax_rows() {
    int bb = blockIdx.y, p = blockIdx.x;
    const float* src = g_t1 + ((size_t)bb * L + p) * L;
    float* dst = g_attn + ((size_t)bb * L + p) * L;
    int tid = threadIdx.x;
    __shared__ float red[8];

    float v[4], mmv[4];
    float mx = -1e30f;
    #pragma unroll
    for (int i = 0; i < 4; i++) {
        int q = tid + 256 * i;
        mmv[i] = g_mmk[q];
        v[i] = src[q] * mmv[i] * 10.0f;
        mx = fmaxf(mx, v[i]);
    }
    #pragma unroll
    for (int o = 16; o; o >>= 1) mx = fmaxf(mx, __shfl_xor_sync(0xffffffffu, mx, o));
    if ((tid & 31) == 0) red[tid >> 5] = mx;
    __syncthreads();
    float m = red[0];
    #pragma unroll
    for (int k = 1; k < 8; k++) m = fmaxf(m, red[k]);
    __syncthreads();

    float e[4];
    float sum = 0.f;
    #pragma unroll
    for (int i = 0; i < 4; i++) {
        e[i] = expf(v[i] - m);
        sum += e[i];
    }
    #pragma unroll
    for (int o = 16; o; o >>= 1) sum += __shfl_xor_sync(0xffffffffu, sum, o);
    if ((tid & 31) == 0) red[tid >> 5] = sum;
    __syncthreads();
    float st = 0.f;
    #pragma unroll
    for (int k = 0; k < 8; k++) st += red[k];
    float inv = 1.0f / st;
    #pragma unroll
    for (int i = 0; i < 4; i++) {
        int q = tid + 256 * i;
        dst[q] = to_tf32(e[i] * inv * mmv[i]);
    }
}

// ---- 10. build raw_w patch matrix W[b][q][c*16+u*4+v] (tf32-rounded) ----
__global__ void k_buildW(const float* __restrict__ b_in) {
    int idx = blockIdx.x * blockDim.x + threadIdx.x;
    if (idx >= NB*L*NCOLS) return;
    int n = idx & (NCOLS - 1);
    int v = n & 3, u = (n >> 2) & 3, c = n >> 4;
    int q = (idx >> 11) & 1023;
    int bb = idx >> 21;
    int qy = q >> 5, qx = q & 31;
    int by = 2 * qy + u - 1, bx = 2 * qx + v - 1;
    float val = 0.f;
    if (by >= 0 && by < 64 && bx >= 0 && bx < 64)
        val = b_in[((size_t)(bb * NC + c)) * 4096 + (size_t)by * 64 + bx];
    g_W[idx] = to_tf32(val);
}

// ---- 11. GEMM2 via tf32 tensor cores ----
// C[p,n] = sum_q A[p,q] * B[q,n];  A = g_attn (M=1024 x K=1024 row-major),
// B = g_W (K=1024 x N=2048 row-major).  128x128 CTA tile, 4 warps of 64x64,
// BK=32, cp.async double buffer.
#define G2_LDA 36
#define G2_LDB 136
#define G2_STAGE (128*G2_LDA + 32*G2_LDB)   // floats per stage

__global__ void __launch_bounds__(128, 2)
mma_gemm2(const float* __restrict__ Aall, const float* __restrict__ Ball,
          float* __restrict__ Call) {
    extern __shared__ float smf[];
    const float* A = Aall + (size_t)blockIdx.z * L * L;
    const float* B = Ball + (size_t)blockIdx.z * (size_t)L * NCOLS;
    float* C = Call + (size_t)blockIdx.z * (size_t)L * NCOLS;
    const int bm = blockIdx.y * 128, bn = blockIdx.x * 128;
    const int tid = threadIdx.x;
    const int warp = tid >> 5, lane = tid & 31;
    const int wm = (warp & 1) << 6, wn = (warp >> 1) << 6;
    const int r8 = lane >> 2, cc = lane & 3;

    float acc[4][8][4];
    #pragma unroll
    for (int mi = 0; mi < 4; mi++)
      #pragma unroll
      for (int ni = 0; ni < 8; ni++)
        #pragma unroll
        for (int k = 0; k < 4; k++) acc[mi][ni][k] = 0.f;

    const float* agp = A + (size_t)(bm + tid) * L;           // row of A, +k0
    const int brow = tid >> 2;
    const int bc = (tid & 3) * 4;                            // float col base
    const float* bgp = B + (size_t)brow * NCOLS + bn + bc;   // +k0*NCOLS

    uint32_t smbase = (uint32_t)__cvta_generic_to_shared(smf);

    // prologue: stage 0
    {
        uint32_t as_ = smbase + (uint32_t)(tid * G2_LDA) * 4u;
        #pragma unroll
        for (int i = 0; i < 8; i++) cp_async16(as_ + i * 16, agp + i * 4);
        uint32_t bs_ = smbase + (uint32_t)(128 * G2_LDA + brow * G2_LDB + bc) * 4u;
        #pragma unroll
        for (int i = 0; i < 8; i++) cp_async16(bs_ + i * 64, bgp + i * 16);
        asm volatile("cp.async.commit_group;");
    }

    int buf = 0;
    for (int kt = 0; kt < 32; kt++) {
        if (kt + 1 < 32) {
            int nb = buf ^ 1;
            uint32_t sb = smbase + (uint32_t)(nb * G2_STAGE) * 4u;
            const float* ag_ = agp + (kt + 1) * 32;
            uint32_t as_ = sb + (uint32_t)(tid * G2_LDA) * 4u;
            #pragma unroll
            for (int i = 0; i < 8; i++) cp_async16(as_ + i * 16, ag_ + i * 4);
            const float* bg_ = bgp + (size_t)(kt + 1) * 32 * NCOLS;
            uint32_t bs_ = sb + (uint32_t)(128 * G2_LDA + brow * G2_LDB + bc) * 4u;
            #pragma unroll
            for (int i = 0; i < 8; i++) cp_async16(bs_ + i * 64, bg_ + i * 16);
            asm volatile("cp.async.commit_group;");
            asm volatile("cp.async.wait_group 1;");
        } else {
            asm volatile("cp.async.wait_group 0;");
        }
        __syncthreads();

        const float* As = smf + buf * G2_STAGE;
        const float* Bs = As + 128 * G2_LDA;
        #pragma unroll
        for (int s = 0; s < 4; s++) {
            const int kk = s * 8;
            uint32_t a[4][4], b[8][2];
            #pragma unroll
            for (int mi = 0; mi < 4; mi++) {
                const float* ap = As + (wm + mi * 16 + r8) * G2_LDA + kk + cc;
                a[mi][0] = __float_as_uint(ap[0]);
                a[mi][1] = __float_as_uint(ap[8 * G2_LDA]);
                a[mi][2] = __float_as_uint(ap[4]);
                a[mi][3] = __float_as_uint(ap[8 * G2_LDA + 4]);
            }
            #pragma unroll
            for (int ni = 0; ni < 8; ni++) {
                const float* bp = Bs + (kk + cc) * G2_LDB + wn + ni * 8 + r8;
                b[ni][0] = __float_as_uint(bp[0]);
                b[ni][1] = __float_as_uint(bp[4 * G2_LDB]);
            }
            #pragma unroll
            for (int mi = 0; mi < 4; mi++)
                #pragma unroll
                for (int ni = 0; ni < 8; ni++)
                    mma_tf32(acc[mi][ni], a[mi], b[ni]);
        }
        __syncthreads();
        buf ^= 1;
    }

    // epilogue
    #pragma unroll
    for (int mi = 0; mi < 4; mi++) {
        int row = bm + wm + mi * 16 + r8;
        #pragma unroll
        for (int ni = 0; ni < 8; ni++) {
            int col = bn + wn + ni * 8 + cc * 2;
            *(float2*)(C + (size_t)row * NCOLS + col) =
                make_float2(acc[mi][ni][0], acc[mi][ni][1]);
            *(float2*)(C + (size_t)(row + 8) * NCOLS + col) =
                make_float2(acc[mi][ni][2], acc[mi][ni][3]);
        }
    }
}

// ---- 12. overlap-add gather (deconv epilogue) ----
__global__ void k_gather(float* __restrict__ out) {
    int idx = blockIdx.x * blockDim.x + threadIdx.x;
    if (idx >= NB*NC*4096) return;
    int ox = idx & 63, oy = (idx >> 6) & 63, c = (idx >> 12) & 127, bb = idx >> 19;
    float s = 0.f;
    int ay = (oy + 1) & 1, ax = (ox + 1) & 1;
    #pragma unroll
    for (int uu = 0; uu < 2; uu++) {
        int u = ay + 2 * uu;
        int t = oy + 1 - u;
        if (t < 0) continue;
        int py = t >> 1;
        if (py >= HG) continue;
        #pragma unroll
        for (int vv = 0; vv < 2; vv++) {
            int v = ax + 2 * vv;
            int t2 = ox + 1 - v;
            if (t2 < 0) continue;
            int px = t2 >> 1;
            if (px >= HG) continue;
            s += g_OP[((size_t)bb * L + py * HG + px) * NCOLS + c * 16 + u * 4 + v];
        }
    }
    out[idx] = 0.25f * s;
}

extern "C" void kernel_launch(void* const* d_in, const int* in_sizes, int n_in,
                              void* d_out, int out_size) {
    (void)in_sizes; (void)n_in; (void)out_size;
    const float* f    = (const float*)d_in[0];
    const float* b    = (const float*)d_in[1];
    const float* mask = (const float*)d_in[2];
    float* out = (float*)d_out;

    float *p_fd, *p_bd, *p_corr, *p_attn, *p_W, *p_OP;
    cudaGetSymbolAddress((void**)&p_fd,   g_fd);
    cudaGetSymbolAddress((void**)&p_bd,   g_bd);
    cudaGetSymbolAddress((void**)&p_corr, g_corr);
    cudaGetSymbolAddress((void**)&p_attn, g_attn);
    cudaGetSymbolAddress((void**)&p_W,    g_W);
    cudaGetSymbolAddress((void**)&p_OP,   g_OP);

    const int g2_smem = 2 * G2_STAGE * 4;   // 71680 bytes
    cudaFuncSetAttribute(mma_gemm2, cudaFuncAttributeMaxDynamicSharedMemorySize, g2_smem);

    k_down<<<(NB*NC*L + 255) / 256, 256>>>(f, b);
    k_ssq<<<(NB*L + 255) / 256, 256>>>();
    k_rnorm<<<(NB*L + 255) / 256, 256>>>();

    // GEMM1: corr[q,p] = sum_c bd[c,q] * fd[c,p]   (M=N=1024, K=128) — fp32
    {
        dim3 grid(L / 128, L / 128, NB);
        sgemm_tn<<<grid, 256>>>(p_bd, p_fd, p_corr, L, L, NC,
                                (size_t)NC * L, (size_t)NC * L, (size_t)L * L);
    }

    k_scores<<<(NB*L*L + 255) / 256, 256>>>();
    k_fuse1<<<(NB*L*L + 255) / 256, 256>>>();
    k_fuse2<<<(NB*L*L + 255) / 256, 256>>>();
    {
        dim3 grid(32, 32, NB);
        dim3 blk(32, 8);
        k_transpose<<<grid, blk>>>();
    }
    k_mm<<<(L + 255) / 256, 256>>>(mask);
    {
        dim3 grid(L, NB);
        k_softmax_rows<<<grid, 256>>>();
    }
    k_buildW<<<(NB*L*NCOLS + 255) / 256, 256>>>(b);

    // GEMM2: OP[p,n] = sum_q attn_t[p,q] * W[q,n]  (M=1024, N=2048, K=1024) — tf32 MMA
    {
        dim3 grid(NCOLS / 128, L / 128, NB);
        mma_gemm2<<<grid, 128, g2_smem>>>(p_attn, p_W, p_OP);
    }

    k_gather<<<(NB*NC*4096 + 255) / 256, 256>>>(out);
}

// round 8
// speedup vs baseline: 2.0983x; 1.0147x over previous
#include <cuda_runtime.h>
#include <math.h>
#include <stdint.h>

#define NB 2
#define NC 128
#define HG 32
#define L 1024
#define NCOLS 2048   // NC * 16

// ---- scratch (device globals; no allocation allowed) ----
__device__ float g_fd[NB*NC*L];
__device__ float g_bd[NB*NC*L];
__device__ float g_ssq[NB*L];
__device__ float g_rnorm[NB*L];
__device__ float g_corr[NB*L*L];   // M[q,p] = sum_c bd[c,q]*fd[c,p]
__device__ float g_sc[NB*L*L];     // normalized 9-tap scores
__device__ float g_t1[NB*L*L];     // fuse pass 1
__device__ float g_fu[NB*L*L];     // fuse pass 2 output [q][p]
__device__ float g_mmk[L];
__device__ float g_attn[NB*L*L];   // attn [b][q][p], tf32-rounded (K-major for GEMM2)
__device__ float g_W[NB*L*NCOLS];  // raw_w patches [b][q][c*16+u*4+v], tf32-rounded
__device__ float g_OP[NB*L*NCOLS]; // deconv GEMM output [b][p][n]

// ---- helpers ----
__device__ __forceinline__ float to_tf32(float x) {
    uint32_t u;
    asm("cvt.rna.tf32.f32 %0, %1;" : "=r"(u) : "f"(x));
    return __uint_as_float(u);
}
__device__ __forceinline__ uint32_t tf32u(float x) {
    uint32_t u;
    asm("cvt.rna.tf32.f32 %0, %1;" : "=r"(u) : "f"(x));
    return u;
}
__device__ __forceinline__ void cp_async16(uint32_t s, const void* g) {
    asm volatile("cp.async.cg.shared.global [%0], [%1], 16;" :: "r"(s), "l"(g));
}
__device__ __forceinline__ void mma_tf32(float* c, const uint32_t* a, const uint32_t* b) {
    asm volatile(
        "mma.sync.aligned.m16n8k8.row.col.f32.tf32.tf32.f32 "
        "{%0,%1,%2,%3}, {%4,%5,%6,%7}, {%8,%9}, {%0,%1,%2,%3};"
        : "+f"(c[0]), "+f"(c[1]), "+f"(c[2]), "+f"(c[3])
        : "r"(a[0]), "r"(a[1]), "r"(a[2]), "r"(a[3]), "r"(b[0]), "r"(b[1]));
}

// ---- 1. downsample by 2 ----
__global__ void k_down(const float* __restrict__ f, const float* __restrict__ b) {
    int idx = blockIdx.x * blockDim.x + threadIdx.x;
    if (idx >= NB*NC*L) return;
    int x = idx & 31, y = (idx >> 5) & 31, c = (idx >> 10) & 127, bb = idx >> 17;
    size_t base = ((size_t)(bb * NC + c)) * 4096 + (size_t)(2*y) * 64 + 2*x;
    g_fd[idx] = f[base];
    g_bd[idx] = b[base];
}

// ---- 2. per-pixel sum over c of bd^2 ----
__global__ void k_ssq() {
    int idx = blockIdx.x * blockDim.x + threadIdx.x;
    if (idx >= NB*L) return;
    int bb = idx >> 10, q = idx & 1023;
    float s = 0.f;
    const float* p = g_bd + (size_t)bb * NC * L + q;
    #pragma unroll 8
    for (int c = 0; c < NC; c++) { float v = p[(size_t)c * L]; s += v * v; }
    g_ssq[idx] = s;
}

// ---- 3. patch inverse norms (3x3, zero pad) ----
__global__ void k_rnorm() {
    int idx = blockIdx.x * blockDim.x + threadIdx.x;
    if (idx >= NB*L) return;
    int bb = idx >> 10, q = idx & 1023;
    int qy = q >> 5, qx = q & 31;
    float s = 1152.0f * 0.0001f;
    for (int dy = -1; dy <= 1; dy++)
      for (int dx = -1; dx <= 1; dx++) {
        int y = qy + dy, x = qx + dx;
        if (y >= 0 && y < HG && x >= 0 && x < HG) s += g_ssq[bb*L + y*HG + x];
      }
    g_rnorm[idx] = 1.0f / sqrtf(s);
}

// =====================================================================
// GEMM1 via 3xTF32 tensor cores (near-fp32 accuracy):
// corr[q,p] = sum_c bd[c,q] * fd[c,p]; A=bd [K=128 c][M=1024 q] K-major,
// B=fd [K][N=1024 p] K-major. 128x128 CTA tile, 4 warps of 64x64, BK=32,
// cp.async double buffer. Dekker split in registers:
//   hi = tf32(x), lo = tf32(x - hi); acc += hi*hi + hi*lo + lo*hi
// =====================================================================
#define G_LD 136
#define G_STAGE (2*32*G_LD)   // floats per stage (A tile + B tile)

__global__ void __launch_bounds__(128, 2)
mma_gemm1(const float* __restrict__ Aall, const float* __restrict__ Ball,
          float* __restrict__ Call) {
    extern __shared__ float smf[];
    const float* A = Aall + (size_t)blockIdx.z * NC * L;
    const float* B = Ball + (size_t)blockIdx.z * NC * L;
    float* C = Call + (size_t)blockIdx.z * (size_t)L * L;
    const int bm = blockIdx.y * 128, bn = blockIdx.x * 128;
    const int tid = threadIdx.x;
    const int warp = tid >> 5, lane = tid & 31;
    const int wm = (warp & 1) << 6, wn = (warp >> 1) << 6;
    const int r8 = lane >> 2, cc = lane & 3;

    float acc[4][8][4];
    #pragma unroll
    for (int mi = 0; mi < 4; mi++)
      #pragma unroll
      for (int ni = 0; ni < 8; ni++)
        #pragma unroll
        for (int k = 0; k < 4; k++) acc[mi][ni][k] = 0.f;

    const int row = tid >> 2, colb = (tid & 3) * 4;
    const float* ag = A + (size_t)row * L + bm + colb;
    const float* bg = B + (size_t)row * L + bn + colb;
    uint32_t smb = (uint32_t)__cvta_generic_to_shared(smf);

    // prologue: stage 0
    {
        uint32_t as_ = smb + (uint32_t)(row * G_LD + colb) * 4u;
        uint32_t bs_ = smb + (uint32_t)(32 * G_LD + row * G_LD + colb) * 4u;
        #pragma unroll
        for (int i = 0; i < 8; i++) {
            cp_async16(as_ + i * 64, ag + i * 16);
            cp_async16(bs_ + i * 64, bg + i * 16);
        }
        asm volatile("cp.async.commit_group;");
    }

    const int NKT = NC / 32;  // 4
    int buf = 0;
    for (int kt = 0; kt < NKT; kt++) {
        if (kt + 1 < NKT) {
            int nb = buf ^ 1;
            uint32_t sb = smb + (uint32_t)(nb * G_STAGE) * 4u;
            const float* ag_ = ag + (size_t)(kt + 1) * 32 * L;
            const float* bg_ = bg + (size_t)(kt + 1) * 32 * L;
            uint32_t as_ = sb + (uint32_t)(row * G_LD + colb) * 4u;
            uint32_t bs_ = sb + (uint32_t)(32 * G_LD + row * G_LD + colb) * 4u;
            #pragma unroll
            for (int i = 0; i < 8; i++) {
                cp_async16(as_ + i * 64, ag_ + i * 16);
                cp_async16(bs_ + i * 64, bg_ + i * 16);
            }
            asm volatile("cp.async.commit_group;");
            asm volatile("cp.async.wait_group 1;");
        } else {
            asm volatile("cp.async.wait_group 0;");
        }
        __syncthreads();

        const float* As = smf + buf * G_STAGE;
        const float* Bs = As + 32 * G_LD;
        #pragma unroll
        for (int s = 0; s < 4; s++) {
            const int kk = s * 8;
            uint32_t ahi[4][4], alo[4][4], bhi[8][2], blo[8][2];
            #pragma unroll
            for (int mi = 0; mi < 4; mi++) {
                const float* ap = As + (kk + cc) * G_LD + wm + mi * 16 + r8;
                float v0 = ap[0], v1 = ap[8], v2 = ap[4 * G_LD], v3 = ap[4 * G_LD + 8];
                ahi[mi][0] = tf32u(v0); alo[mi][0] = tf32u(v0 - __uint_as_float(ahi[mi][0]));
                ahi[mi][1] = tf32u(v1); alo[mi][1] = tf32u(v1 - __uint_as_float(ahi[mi][1]));
                ahi[mi][2] = tf32u(v2); alo[mi][2] = tf32u(v2 - __uint_as_float(ahi[mi][2]));
                ahi[mi][3] = tf32u(v3); alo[mi][3] = tf32u(v3 - __uint_as_float(ahi[mi][3]));
            }
            #pragma unroll
            for (int ni = 0; ni < 8; ni++) {
                const float* bp = Bs + (kk + cc) * G_LD + wn + ni * 8 + r8;
                float v0 = bp[0], v1 = bp[4 * G_LD];
                bhi[ni][0] = tf32u(v0); blo[ni][0] = tf32u(v0 - __uint_as_float(bhi[ni][0]));
                bhi[ni][1] = tf32u(v1); blo[ni][1] = tf32u(v1 - __uint_as_float(bhi[ni][1]));
            }
            #pragma unroll
            for (int mi = 0; mi < 4; mi++)
                #pragma unroll
                for (int ni = 0; ni < 8; ni++) {
                    mma_tf32(acc[mi][ni], ahi[mi], bhi[ni]);
                    mma_tf32(acc[mi][ni], ahi[mi], blo[ni]);
                    mma_tf32(acc[mi][ni], alo[mi], bhi[ni]);
                }
        }
        __syncthreads();
        buf ^= 1;
    }

    #pragma unroll
    for (int mi = 0; mi < 4; mi++) {
        int r = bm + wm + mi * 16 + r8;
        #pragma unroll
        for (int ni = 0; ni < 8; ni++) {
            int col = bn + wn + ni * 8 + cc * 2;
            *(float2*)(C + (size_t)r * L + col) =
                make_float2(acc[mi][ni][0], acc[mi][ni][1]);
            *(float2*)(C + (size_t)(r + 8) * L + col) =
                make_float2(acc[mi][ni][2], acc[mi][ni][3]);
        }
    }
}

// ---- 5. 9-tap diagonal patch stencil + normalize ----
__global__ void k_scores() {
    int idx = blockIdx.x * blockDim.x + threadIdx.x;
    if (idx >= NB*L*L) return;
    int px = idx & 31, py = (idx >> 5) & 31, qx = (idx >> 10) & 31, qy = (idx >> 15) & 31;
    int bb = idx >> 20;
    const float* M = g_corr + (size_t)bb * L * L;
    float s = 0.f;
    #pragma unroll
    for (int dy = -1; dy <= 1; dy++) {
        int qy2 = qy + dy, py2 = py + dy;
        if (qy2 < 0 || qy2 >= HG || py2 < 0 || py2 >= HG) continue;
        #pragma unroll
        for (int dx = -1; dx <= 1; dx++) {
            int qx2 = qx + dx, px2 = px + dx;
            if (qx2 < 0 || qx2 >= HG || px2 < 0 || px2 >= HG) continue;
            s += M[(size_t)(qy2 * HG + qx2) * L + (py2 * HG + px2)];
        }
    }
    g_sc[idx] = s * g_rnorm[bb * L + qy * HG + qx];
}

// ---- 6. fuse pass 1: diagonal 3-tap on flattened (1024,1024) ----
__global__ void k_fuse1() {
    int idx = blockIdx.x * blockDim.x + threadIdx.x;
    if (idx >= NB*L*L) return;
    int j = idx & 1023, i = (idx >> 10) & 1023;
    float s = g_sc[idx];
    if (i > 0 && j > 0)       s += g_sc[idx - L - 1];
    if (i < 1023 && j < 1023) s += g_sc[idx + L + 1];
    g_t1[idx] = s;
}

// ---- 7. fuse pass 2: transposed flattening, diagonal 3-tap, untranspose ----
__global__ void k_fuse2() {
    int idx = blockIdx.x * blockDim.x + threadIdx.x;
    if (idx >= NB*L*L) return;
    int wf = idx & 31, hf = (idx >> 5) & 31, wb = (idx >> 10) & 31, hb = (idx >> 15) & 31;
    int bb = idx >> 20;
    int i2b = wb * HG + hb, j2b = wf * HG + hf;
    const float* T = g_t1 + (size_t)bb * L * L;
    float s = 0.f;
    #pragma unroll
    for (int d = -1; d <= 1; d++) {
        int i2 = i2b + d, j2 = j2b + d;
        if (i2 < 0 || i2 >= L || j2 < 0 || j2 >= L) continue;
        int hb2 = i2 & 31, wb2 = i2 >> 5, hf2 = j2 & 31, wf2 = j2 >> 5;
        s += T[(size_t)(hb2 * HG + wb2) * L + (hf2 * HG + wf2)];
    }
    g_fu[idx] = s;
}

// ---- 8. mask gate (batch 0 of mask) ----
__global__ void k_mm(const float* __restrict__ mask) {
    int q = blockIdx.x * blockDim.x + threadIdx.x;
    if (q >= L) return;
    int qy = q >> 5, qx = q & 31;
    float s = 0.f;
    for (int dy = -1; dy <= 1; dy++)
      for (int dx = -1; dx <= 1; dx++) {
        int y = qy + dy, x = qx + dx;
        if (y >= 0 && y < HG && x >= 0 && x < HG)
            s += mask[(size_t)(8 * y) * 256 + 8 * x];
      }
    g_mmk[q] = (s == 0.0f) ? 1.0f : 0.0f;
}

// ---- 9. softmax over q per (b,p): reads g_fu [q][p], writes g_attn [q][p] tf32 ----
__global__ void k_softmax() {
    int bb = blockIdx.y;
    int p = blockIdx.x * 32 + threadIdx.x;
    int tx = threadIdx.x, ty = threadIdx.y;
    __shared__ float red[8][32];
    const float* src = g_fu + (size_t)bb * L * L;
    float* dst = g_attn + (size_t)bb * L * L;
    float mx = -1e30f;
    for (int q = ty; q < L; q += 8) {
        float v = src[(size_t)q * L + p] * g_mmk[q] * 10.0f;
        mx = fmaxf(mx, v);
    }
    red[ty][tx] = mx; __syncthreads();
    if (ty == 0) {
        float m = red[0][tx];
        #pragma unroll
        for (int k = 1; k < 8; k++) m = fmaxf(m, red[k][tx]);
        red[0][tx] = m;
    }
    __syncthreads();
    mx = red[0][tx];
    __syncthreads();
    float sm = 0.f;
    for (int q = ty; q < L; q += 8) {
        float v = src[(size_t)q * L + p] * g_mmk[q] * 10.0f;
        float e = expf(v - mx);
        dst[(size_t)q * L + p] = e;
        sm += e;
    }
    red[ty][tx] = sm; __syncthreads();
    if (ty == 0) {
        float s = 0.f;
        #pragma unroll
        for (int k = 0; k < 8; k++) s += red[k][tx];
        red[0][tx] = s;
    }
    __syncthreads();
    float inv = 1.0f / red[0][tx];
    for (int q = ty; q < L; q += 8)
        dst[(size_t)q * L + p] = to_tf32(dst[(size_t)q * L + p] * inv * g_mmk[q]);
}

// ---- 10. build raw_w patch matrix W[b][q][c*16+u*4+v] (tf32-rounded) ----
__global__ void k_buildW(const float* __restrict__ b_in) {
    int idx = blockIdx.x * blockDim.x + threadIdx.x;
    if (idx >= NB*L*NCOLS) return;
    int n = idx & (NCOLS - 1);
    int v = n & 3, u = (n >> 2) & 3, c = n >> 4;
    int q = (idx >> 11) & 1023;
    int bb = idx >> 21;
    int qy = q >> 5, qx = q & 31;
    int by = 2 * qy + u - 1, bx = 2 * qx + v - 1;
    float val = 0.f;
    if (by >= 0 && by < 64 && bx >= 0 && bx < 64)
        val = b_in[((size_t)(bb * NC + c)) * 4096 + (size_t)by * 64 + bx];
    g_W[idx] = to_tf32(val);
}

// =====================================================================
// GEMM2 via tf32 tensor cores:
// OP[p,n] = sum_q attn[q,p] * W[q,n]; A = g_attn [K=1024 q][M=1024 p]
// K-major, B = g_W [K][N=2048] K-major. Same tiling as GEMM1, 1x tf32
// (inputs pre-rounded at producers).
// =====================================================================
__global__ void __launch_bounds__(128, 2)
mma_gemm2(const float* __restrict__ Aall, const float* __restrict__ Ball,
          float* __restrict__ Call) {
    extern __shared__ float smf[];
    const float* A = Aall + (size_t)blockIdx.z * L * L;
    const float* B = Ball + (size_t)blockIdx.z * (size_t)L * NCOLS;
    float* C = Call + (size_t)blockIdx.z * (size_t)L * NCOLS;
    const int bm = blockIdx.y * 128, bn = blockIdx.x * 128;
    const int tid = threadIdx.x;
    const int warp = tid >> 5, lane = tid & 31;
    const int wm = (warp & 1) << 6, wn = (warp >> 1) << 6;
    const int r8 = lane >> 2, cc = lane & 3;

    float acc[4][8][4];
    #pragma unroll
    for (int mi = 0; mi < 4; mi++)
      #pragma unroll
      for (int ni = 0; ni < 8; ni++)
        #pragma unroll
        for (int k = 0; k < 4; k++) acc[mi][ni][k] = 0.f;

    const int row = tid >> 2, colb = (tid & 3) * 4;
    const float* ag = A + (size_t)row * L + bm + colb;
    const float* bg = B + (size_t)row * NCOLS + bn + colb;
    uint32_t smb = (uint32_t)__cvta_generic_to_shared(smf);

    // prologue: stage 0
    {
        uint32_t as_ = smb + (uint32_t)(row * G_LD + colb) * 4u;
        uint32_t bs_ = smb + (uint32_t)(32 * G_LD + row * G_LD + colb) * 4u;
        #pragma unroll
        for (int i = 0; i < 8; i++) {
            cp_async16(as_ + i * 64, ag + i * 16);
            cp_async16(bs_ + i * 64, bg + i * 16);
        }
        asm volatile("cp.async.commit_group;");
    }

    int buf = 0;
    for (int kt = 0; kt < 32; kt++) {
        if (kt + 1 < 32) {
            int nb = buf ^ 1;
            uint32_t sb = smb + (uint32_t)(nb * G_STAGE) * 4u;
            const float* ag_ = ag + (size_t)(kt + 1) * 32 * L;
            const float* bg_ = bg + (size_t)(kt + 1) * 32 * NCOLS;
            uint32_t as_ = sb + (uint32_t)(row * G_LD + colb) * 4u;
            uint32_t bs_ = sb + (uint32_t)(32 * G_LD + row * G_LD + colb) * 4u;
            #pragma unroll
            for (int i = 0; i < 8; i++) {
                cp_async16(as_ + i * 64, ag_ + i * 16);
                cp_async16(bs_ + i * 64, bg_ + i * 16);
            }
            asm volatile("cp.async.commit_group;");
            asm volatile("cp.async.wait_group 1;");
        } else {
            asm volatile("cp.async.wait_group 0;");
        }
        __syncthreads();

        const float* As = smf + buf * G_STAGE;
        const float* Bs = As + 32 * G_LD;
        #pragma unroll
        for (int s = 0; s < 4; s++) {
            const int kk = s * 8;
            uint32_t a[4][4], b[8][2];
            #pragma unroll
            for (int mi = 0; mi < 4; mi++) {
                const float* ap = As + (kk + cc) * G_LD + wm + mi * 16 + r8;
                a[mi][0] = __float_as_uint(ap[0]);
                a[mi][1] = __float_as_uint(ap[8]);
                a[mi][2] = __float_as_uint(ap[4 * G_LD]);
                a[mi][3] = __float_as_uint(ap[4 * G_LD + 8]);
            }
            #pragma unroll
            for (int ni = 0; ni < 8; ni++) {
                const float* bp = Bs + (kk + cc) * G_LD + wn + ni * 8 + r8;
                b[ni][0] = __float_as_uint(bp[0]);
                b[ni][1] = __float_as_uint(bp[4 * G_LD]);
            }
            #pragma unroll
            for (int mi = 0; mi < 4; mi++)
                #pragma unroll
                for (int ni = 0; ni < 8; ni++)
                    mma_tf32(acc[mi][ni], a[mi], b[ni]);
        }
        __syncthreads();
        buf ^= 1;
    }

    #pragma unroll
    for (int mi = 0; mi < 4; mi++) {
        int r = bm + wm + mi * 16 + r8;
        #pragma unroll
        for (int ni = 0; ni < 8; ni++) {
            int col = bn + wn + ni * 8 + cc * 2;
            *(float2*)(C + (size_t)r * NCOLS + col) =
                make_float2(acc[mi][ni][0], acc[mi][ni][1]);
            *(float2*)(C + (size_t)(r + 8) * NCOLS + col) =
                make_float2(acc[mi][ni][2], acc[mi][ni][3]);
        }
    }
}

// ---- 12. overlap-add gather (deconv epilogue) ----
__global__ void k_gather(float* __restrict__ out) {
    int idx = blockIdx.x * blockDim.x + threadIdx.x;
    if (idx >= NB*NC*4096) return;
    int ox = idx & 63, oy = (idx >> 6) & 63, c = (idx >> 12) & 127, bb = idx >> 19;
    float s = 0.f;
    int ay = (oy + 1) & 1, ax = (ox + 1) & 1;
    #pragma unroll
    for (int uu = 0; uu < 2; uu++) {
        int u = ay + 2 * uu;
        int t = oy + 1 - u;
        if (t < 0) continue;
        int py = t >> 1;
        if (py >= HG) continue;
        #pragma unroll
        for (int vv = 0; vv < 2; vv++) {
            int v = ax + 2 * vv;
            int t2 = ox + 1 - v;
            if (t2 < 0) continue;
            int px = t2 >> 1;
            if (px >= HG) continue;
            s += g_OP[((size_t)bb * L + py * HG + px) * NCOLS + c * 16 + u * 4 + v];
        }
    }
    out[idx] = 0.25f * s;
}

extern "C" void kernel_launch(void* const* d_in, const int* in_sizes, int n_in,
                              void* d_out, int out_size) {
    (void)in_sizes; (void)n_in; (void)out_size;
    const float* f    = (const float*)d_in[0];
    const float* b    = (const float*)d_in[1];
    const float* mask = (const float*)d_in[2];
    float* out = (float*)d_out;

    float *p_fd, *p_bd, *p_corr, *p_attn, *p_W, *p_OP;
    cudaGetSymbolAddress((void**)&p_fd,   g_fd);
    cudaGetSymbolAddress((void**)&p_bd,   g_bd);
    cudaGetSymbolAddress((void**)&p_corr, g_corr);
    cudaGetSymbolAddress((void**)&p_attn, g_attn);
    cudaGetSymbolAddress((void**)&p_W,    g_W);
    cudaGetSymbolAddress((void**)&p_OP,   g_OP);

    const int g_smem = 2 * G_STAGE * 4;   // 69632 bytes
    cudaFuncSetAttribute(mma_gemm1, cudaFuncAttributeMaxDynamicSharedMemorySize, g_smem);
    cudaFuncSetAttribute(mma_gemm2, cudaFuncAttributeMaxDynamicSharedMemorySize, g_smem);

    k_down<<<(NB*NC*L + 255) / 256, 256>>>(f, b);
    k_ssq<<<(NB*L + 255) / 256, 256>>>();
    k_rnorm<<<(NB*L + 255) / 256, 256>>>();

    // GEMM1: corr[q,p] = sum_c bd[c,q] * fd[c,p]  (M=N=1024, K=128) — 3xTF32 MMA
    {
        dim3 grid(L / 128, L / 128, NB);
        mma_gemm1<<<grid, 128, g_smem>>>(p_bd, p_fd, p_corr);
    }

    k_scores<<<(NB*L*L + 255) / 256, 256>>>();
    k_fuse1<<<(NB*L*L + 255) / 256, 256>>>();
    k_fuse2<<<(NB*L*L + 255) / 256, 256>>>();
    k_mm<<<(L + 255) / 256, 256>>>(mask);
    {
        dim3 grid(L / 32, NB);
        dim3 blk(32, 8);
        k_softmax<<<grid, blk>>>();
    }
    k_buildW<<<(NB*L*NCOLS + 255) / 256, 256>>>(b);

    // GEMM2: OP[p,n] = sum_q attn[q,p] * W[q,n]  (M=1024, N=2048, K=1024) — tf32 MMA
    {
        dim3 grid(NCOLS / 128, L / 128, NB);
        mma_gemm2<<<grid, 128, g_smem>>>(p_attn, p_W, p_OP);
    }

    k_gather<<<(NB*NC*4096 + 255) / 256, 256>>>(out);
}